// round 1
// baseline (speedup 1.0000x reference)
#include <cuda_runtime.h>

#define P 65536          // 64*64*16 spatial positions
#define CH 64
#define NHEAD 8
#define DH 8

// ---------------- scratch (no allocations allowed) ----------------
__device__ float g_xu[CH * P];   // upsampled x, channel-major [c][p]
__device__ float g_q[P * CH];    // position-major [p][head*8+d], pre-scaled
__device__ float g_k[P * CH];
__device__ float g_v[P * CH];
__device__ float g_mean[128];    // [0:64] skip, [64:128] xu
__device__ float g_inv[128];

// ---------------- kernel 1: trilinear upsample x (32,32,8)->(64,64,16) ----------------
__global__ __launch_bounds__(256) void k_upsample(const float* __restrict__ x) {
    int idx = blockIdx.x * 256 + threadIdx.x;        // 64*65536 threads
    int c = idx >> 16;
    int p = idx & 65535;
    int h = p >> 10, w = (p >> 4) & 63, z = p & 15;

    float ph = (float)h * (31.0f / 63.0f);
    int h0 = min((int)ph, 30); float fh = ph - (float)h0;
    float pw = (float)w * (31.0f / 63.0f);
    int w0 = min((int)pw, 30); float fw = pw - (float)w0;
    float pz = (float)z * (7.0f / 15.0f);
    int z0 = min((int)pz, 6);  float fz = pz - (float)z0;

    const float* xb = x + c * 8192 + h0 * 256 + w0 * 8 + z0;
    float c000 = xb[0],   c001 = xb[1];
    float c010 = xb[8],   c011 = xb[9];
    float c100 = xb[256], c101 = xb[257];
    float c110 = xb[264], c111 = xb[265];

    float a00 = c000 + (c001 - c000) * fz;
    float a01 = c010 + (c011 - c010) * fz;
    float a10 = c100 + (c101 - c100) * fz;
    float a11 = c110 + (c111 - c110) * fz;
    float b0  = a00 + (a01 - a00) * fw;
    float b1  = a10 + (a11 - a10) * fw;
    g_xu[idx] = b0 + (b1 - b0) * fh;
}

// ---------------- kernel 2: per-channel instance-norm stats ----------------
__global__ __launch_bounds__(256) void k_stats(const float* __restrict__ skip) {
    int b = blockIdx.x;  // 0..127
    const float* src = (b < 64) ? (skip + (size_t)b * P) : (g_xu + (size_t)(b - 64) * P);
    float s = 0.f, s2 = 0.f;
    for (int i = threadIdx.x; i < P; i += 256) {
        float v = src[i];
        s += v; s2 += v * v;
    }
    __shared__ float rs[256], rs2[256];
    int t = threadIdx.x;
    rs[t] = s; rs2[t] = s2;
    __syncthreads();
    for (int ofs = 128; ofs > 0; ofs >>= 1) {
        if (t < ofs) { rs[t] += rs[t + ofs]; rs2[t] += rs2[t + ofs]; }
        __syncthreads();
    }
    if (t == 0) {
        float m = rs[0] * (1.0f / P);
        float var = rs2[0] * (1.0f / P) - m * m;
        g_mean[b] = m;
        g_inv[b]  = rsqrtf(var + 1e-5f);
    }
}

// ---------------- kernel 3: fused norm + QKV projection ----------------
// block = 64 positions; thread computes 2 output channels x 8 positions x 3 mats
__global__ __launch_bounds__(256) void k_qkv(
    const float* __restrict__ skip,
    const float* __restrict__ Wq, const float* __restrict__ bq,
    const float* __restrict__ Wk, const float* __restrict__ bk,
    const float* __restrict__ Wv, const float* __restrict__ bv)
{
    __shared__ float sA[64 * 65];  // normalized skip  [c][p]
    __shared__ float sB[64 * 65];  // normalized xu    [c][p]

    int p0 = blockIdx.x * 64;
    int t = threadIdx.x;

    for (int i = t; i < 4096; i += 256) {
        int c = i >> 6, pl = i & 63;
        float a = skip[(size_t)c * P + p0 + pl];
        sA[c * 65 + pl] = (a - g_mean[c]) * g_inv[c];
        float bvv = g_xu[(size_t)c * P + p0 + pl];
        sB[c * 65 + pl] = (bvv - g_mean[64 + c]) * g_inv[64 + c];
    }
    __syncthreads();

    int cg = t & 31;         // output-channel pair index
    int pg = t >> 5;         // 0..7 -> positions pg*8 .. pg*8+7
    int co = cg * 2;

    float accq[2][8], acck[2][8], accv[2][8];
    #pragma unroll
    for (int j = 0; j < 8; j++) {
        accq[0][j] = 0.f; accq[1][j] = 0.f;
        acck[0][j] = 0.f; acck[1][j] = 0.f;
        accv[0][j] = 0.f; accv[1][j] = 0.f;
    }

    const float* baseA = sA + pg * 8;
    const float* baseB = sB + pg * 8;

    #pragma unroll 4
    for (int c = 0; c < 64; c++) {
        float ina[8], inb[8];
        #pragma unroll
        for (int j = 0; j < 8; j++) {
            ina[j] = baseA[c * 65 + j];
            inb[j] = baseB[c * 65 + j];
        }
        float2 wq = *(const float2*)(Wq + c * 64 + co);
        float2 wk = *(const float2*)(Wk + c * 64 + co);
        float2 wv = *(const float2*)(Wv + c * 64 + co);
        #pragma unroll
        for (int j = 0; j < 8; j++) {
            accq[0][j] += ina[j] * wq.x;  accq[1][j] += ina[j] * wq.y;
            acck[0][j] += inb[j] * wk.x;  acck[1][j] += inb[j] * wk.y;
            accv[0][j] += inb[j] * wv.x;  accv[1][j] += inb[j] * wv.y;
        }
    }

    const float scale = 0.35355339059327373f;  // 1/sqrt(8)
    float2 bq2 = *(const float2*)(bq + co);
    float2 bk2 = *(const float2*)(bk + co);
    float2 bv2 = *(const float2*)(bv + co);

    #pragma unroll
    for (int j = 0; j < 8; j++) {
        int p = p0 + pg * 8 + j;
        float2 q2; q2.x = (accq[0][j] + bq2.x) * scale; q2.y = (accq[1][j] + bq2.y) * scale;
        float2 k2; k2.x =  acck[0][j] + bk2.x;          k2.y =  acck[1][j] + bk2.y;
        float2 v2; v2.x =  accv[0][j] + bv2.x;          v2.y =  accv[1][j] + bv2.y;
        *(float2*)(g_q + (size_t)p * 64 + co) = q2;
        *(float2*)(g_k + (size_t)p * 64 + co) = k2;
        *(float2*)(g_v + (size_t)p * 64 + co) = v2;
    }
}

// ---------------- kernel 4: neighborhood attention + output projection ----------------
// block = 32 positions; thread = (position, head) for attention phase
__global__ __launch_bounds__(256) void k_attn(
    const float* __restrict__ Wo, const float* __restrict__ bo,
    const float* __restrict__ rpb, float* __restrict__ out)
{
    __shared__ float sRpb[1000];
    __shared__ float sWo[4096];
    __shared__ float sO[32 * 65];

    int t = threadIdx.x;
    for (int i = t; i < 1000; i += 256) sRpb[i] = rpb[i];
    for (int i = t; i < 4096; i += 256) sWo[i] = Wo[i];
    __syncthreads();

    int p0 = blockIdx.x * 32;
    int pl = t >> 3;
    int head = t & 7;
    int p = p0 + pl;
    int h = p >> 10, w = (p >> 4) & 63, z = p & 15;
    int sh = min(max(h - 1, 0), 61);
    int sw = min(max(w - 1, 0), 61);
    int sz = min(max(z - 1, 0), 13);

    int off = head * 8;
    const float4* qp = (const float4*)(g_q + (size_t)p * 64 + off);
    float4 q0 = qp[0], q1 = qp[1];

    const float* rp = sRpb + head * 125 + (sh - h + 2) * 25 + (sw - w + 2) * 5 + (sz - z + 2);

    float logit[27];
    float mx = -1e30f;
    #pragma unroll
    for (int a = 0; a < 3; a++) {
        #pragma unroll
        for (int b = 0; b < 3; b++) {
            int nbase = (((sh + a) * 64 + sw + b) * 16 + sz) * 64 + off;
            #pragma unroll
            for (int cz = 0; cz < 3; cz++) {
                const float4* kp = (const float4*)(g_k + nbase + cz * 64);
                float4 k0 = kp[0], k1 = kp[1];
                float l = q0.x * k0.x + q0.y * k0.y + q0.z * k0.z + q0.w * k0.w
                        + q1.x * k1.x + q1.y * k1.y + q1.z * k1.z + q1.w * k1.w;
                l += rp[a * 25 + b * 5 + cz];
                logit[a * 9 + b * 3 + cz] = l;
                mx = fmaxf(mx, l);
            }
        }
    }
    float se = 0.f;
    #pragma unroll
    for (int m = 0; m < 27; m++) {
        float e = __expf(logit[m] - mx);
        logit[m] = e;
        se += e;
    }
    float inv = 1.0f / se;

    float o[8];
    #pragma unroll
    for (int j = 0; j < 8; j++) o[j] = 0.f;
    #pragma unroll
    for (int a = 0; a < 3; a++) {
        #pragma unroll
        for (int b = 0; b < 3; b++) {
            int nbase = (((sh + a) * 64 + sw + b) * 16 + sz) * 64 + off;
            #pragma unroll
            for (int cz = 0; cz < 3; cz++) {
                const float4* vp = (const float4*)(g_v + nbase + cz * 64);
                float4 v0 = vp[0], v1 = vp[1];
                float wt = logit[a * 9 + b * 3 + cz] * inv;
                o[0] += wt * v0.x; o[1] += wt * v0.y; o[2] += wt * v0.z; o[3] += wt * v0.w;
                o[4] += wt * v1.x; o[5] += wt * v1.y; o[6] += wt * v1.z; o[7] += wt * v1.w;
            }
        }
    }
    float* so = sO + pl * 65 + off;
    #pragma unroll
    for (int j = 0; j < 8; j++) so[j] = o[j];
    __syncthreads();

    // output projection: warp wi -> channels wi*8..wi*8+7, lane -> position
    int lane = t & 31, wi = t >> 5;
    const float* row = sO + lane * 65;
    float acc[8];
    #pragma unroll
    for (int j = 0; j < 8; j++) acc[j] = bo[wi * 8 + j];
    for (int c = 0; c < 64; c++) {
        float rv = row[c];
        const float* wrow = sWo + c * 64 + wi * 8;
        #pragma unroll
        for (int j = 0; j < 8; j++) acc[j] += rv * wrow[j];
    }
    #pragma unroll
    for (int j = 0; j < 8; j++) {
        int co = wi * 8 + j;
        out[(size_t)co * P + p0 + lane] = acc[j];
    }
}

// ---------------- launch ----------------
extern "C" void kernel_launch(void* const* d_in, const int* in_sizes, int n_in,
                              void* d_out, int out_size) {
    const float* x    = (const float*)d_in[0];
    const float* skip = (const float*)d_in[1];
    const float* Wq   = (const float*)d_in[2];
    const float* bq   = (const float*)d_in[3];
    const float* Wk   = (const float*)d_in[4];
    const float* bk   = (const float*)d_in[5];
    const float* Wv   = (const float*)d_in[6];
    const float* bv   = (const float*)d_in[7];
    const float* Wo   = (const float*)d_in[8];
    const float* bo   = (const float*)d_in[9];
    const float* rpb  = (const float*)d_in[10];
    float* out = (float*)d_out;

    k_upsample<<<16384, 256>>>(x);
    k_stats<<<128, 256>>>(skip);
    k_qkv<<<1024, 256>>>(skip, Wq, bq, Wk, bk, Wv, bv);
    k_attn<<<2048, 256>>>(Wo, bo, rpb, out);
}

// round 2
// speedup vs baseline: 1.0332x; 1.0332x over previous
#include <cuda_runtime.h>

#define P 65536
typedef unsigned long long u64;

// ---------------- scratch ----------------
__device__ float g_xu[64 * P];   // upsampled x, channel-major [c][p]
__device__ float g_q[P * 64];    // position-major [p][c], pre-scaled
__device__ float g_k[P * 64];
__device__ float g_v[P * 64];
__device__ float g_mean[128];    // [0:64] skip, [64:128] xu
__device__ float g_inv[128];
__device__ float g_p1[64 * 256]; // per-block partial sums for xu stats
__device__ float g_p2[64 * 256];

// ---------------- f32x2 helpers ----------------
__device__ __forceinline__ u64 dup2(float v) {
    u64 r; asm("mov.b64 %0,{%1,%1};" : "=l"(r) : "f"(v)); return r;
}
__device__ __forceinline__ void fma2(u64& a, u64 x, u64 y) {
    asm("fma.rn.f32x2 %0,%1,%2,%0;" : "+l"(a) : "l"(x), "l"(y));
}
__device__ __forceinline__ float2 unp2(u64 v) {
    float2 r; asm("mov.b64 {%0,%1},%2;" : "=f"(r.x), "=f"(r.y) : "l"(v)); return r;
}

// ---------------- kernel 1: trilinear upsample + xu stat partials ----------------
__global__ __launch_bounds__(256) void k_upsample(const float* __restrict__ x) {
    int t = threadIdx.x;
    int idx = blockIdx.x * 256 + t;
    int c = idx >> 16;
    int p = idx & 65535;
    int h = p >> 10, w = (p >> 4) & 63, z = p & 15;

    float ph = (float)h * (31.0f / 63.0f);
    int h0 = min((int)ph, 30); float fh = ph - (float)h0;
    float pw = (float)w * (31.0f / 63.0f);
    int w0 = min((int)pw, 30); float fw = pw - (float)w0;
    float pz = (float)z * (7.0f / 15.0f);
    int z0 = min((int)pz, 6);  float fz = pz - (float)z0;

    const float* xb = x + c * 8192 + h0 * 256 + w0 * 8 + z0;
    float c000 = xb[0],   c001 = xb[1];
    float c010 = xb[8],   c011 = xb[9];
    float c100 = xb[256], c101 = xb[257];
    float c110 = xb[264], c111 = xb[265];

    float a00 = c000 + (c001 - c000) * fz;
    float a01 = c010 + (c011 - c010) * fz;
    float a10 = c100 + (c101 - c100) * fz;
    float a11 = c110 + (c111 - c110) * fz;
    float b0  = a00 + (a01 - a00) * fw;
    float b1  = a10 + (a11 - a10) * fw;
    float val = b0 + (b1 - b0) * fh;
    g_xu[idx] = val;

    // deterministic block-level partial sums (all threads in block share c)
    float s = val, s2 = val * val;
    #pragma unroll
    for (int o = 16; o; o >>= 1) {
        s  += __shfl_down_sync(0xffffffffu, s,  o);
        s2 += __shfl_down_sync(0xffffffffu, s2, o);
    }
    __shared__ float ws1[8], ws2[8];
    if ((t & 31) == 0) { ws1[t >> 5] = s; ws2[t >> 5] = s2; }
    __syncthreads();
    if (t == 0) {
        float a = 0.f, b = 0.f;
        #pragma unroll
        for (int i = 0; i < 8; i++) { a += ws1[i]; b += ws2[i]; }
        int cc = blockIdx.x >> 8, binc = blockIdx.x & 255;
        g_p1[cc * 256 + binc] = a;
        g_p2[cc * 256 + binc] = b;
    }
}

// ---------------- kernel 2: stats (skip full pass; xu from partials) ----------------
__global__ __launch_bounds__(256) void k_stats(const float* __restrict__ skip) {
    int b = blockIdx.x;
    int t = threadIdx.x;
    __shared__ float rs[256], rs2[256];
    float s = 0.f, s2 = 0.f;
    if (b < 64) {
        const float* src = skip + (size_t)b * P;
        for (int i = t; i < P; i += 256) {
            float v = src[i];
            s += v; s2 += v * v;
        }
    } else {
        int c = b - 64;
        s = g_p1[c * 256 + t];
        s2 = g_p2[c * 256 + t];
    }
    rs[t] = s; rs2[t] = s2;
    __syncthreads();
    for (int ofs = 128; ofs > 0; ofs >>= 1) {
        if (t < ofs) { rs[t] += rs[t + ofs]; rs2[t] += rs2[t + ofs]; }
        __syncthreads();
    }
    if (t == 0) {
        float m = rs[0] * (1.0f / P);
        float var = rs2[0] * (1.0f / P) - m * m;
        g_mean[b] = m;
        g_inv[b]  = rsqrtf(var + 1e-5f);
    }
}

// ---------------- kernel 3: fused norm + QKV projection (f32x2) ----------------
__global__ __launch_bounds__(256) void k_qkv(
    const float* __restrict__ skip,
    const float* __restrict__ Wq, const float* __restrict__ bq,
    const float* __restrict__ Wk, const float* __restrict__ bk,
    const float* __restrict__ Wv, const float* __restrict__ bv)
{
    __shared__ float sA[64 * 66];  // normalized skip  [c][p], pad 66 (8B-aligned rows)
    __shared__ float sB[64 * 66];  // normalized xu

    int p0 = blockIdx.x * 64;
    int t = threadIdx.x;

    for (int i = t; i < 4096; i += 256) {
        int c = i >> 6, pl = i & 63;
        sA[c * 66 + pl] = (skip[(size_t)c * P + p0 + pl] - g_mean[c]) * g_inv[c];
        sB[c * 66 + pl] = (g_xu[(size_t)c * P + p0 + pl] - g_mean[64 + c]) * g_inv[64 + c];
    }
    __syncthreads();

    int cg = t & 31, pg = t >> 5;
    int co = cg * 2;

    u64 aq[2][4], ak[2][4], av[2][4];
    #pragma unroll
    for (int j = 0; j < 4; j++) {
        aq[0][j] = 0ull; aq[1][j] = 0ull;
        ak[0][j] = 0ull; ak[1][j] = 0ull;
        av[0][j] = 0ull; av[1][j] = 0ull;
    }

    const float* bA = sA + pg * 8;
    const float* bB = sB + pg * 8;

    #pragma unroll 2
    for (int c = 0; c < 64; c++) {
        const u64* pa = (const u64*)(bA + c * 66);
        const u64* pb = (const u64*)(bB + c * 66);
        u64 a0 = pa[0], a1 = pa[1], a2 = pa[2], a3 = pa[3];
        u64 b0 = pb[0], b1 = pb[1], b2 = pb[2], b3 = pb[3];

        float2 wq = *(const float2*)(Wq + c * 64 + co);
        float2 wk = *(const float2*)(Wk + c * 64 + co);
        float2 wv = *(const float2*)(Wv + c * 64 + co);
        u64 wq0 = dup2(wq.x), wq1 = dup2(wq.y);
        u64 wk0 = dup2(wk.x), wk1 = dup2(wk.y);
        u64 wv0 = dup2(wv.x), wv1 = dup2(wv.y);

        fma2(aq[0][0], a0, wq0); fma2(aq[0][1], a1, wq0); fma2(aq[0][2], a2, wq0); fma2(aq[0][3], a3, wq0);
        fma2(aq[1][0], a0, wq1); fma2(aq[1][1], a1, wq1); fma2(aq[1][2], a2, wq1); fma2(aq[1][3], a3, wq1);
        fma2(ak[0][0], b0, wk0); fma2(ak[0][1], b1, wk0); fma2(ak[0][2], b2, wk0); fma2(ak[0][3], b3, wk0);
        fma2(ak[1][0], b0, wk1); fma2(ak[1][1], b1, wk1); fma2(ak[1][2], b2, wk1); fma2(ak[1][3], b3, wk1);
        fma2(av[0][0], b0, wv0); fma2(av[0][1], b1, wv0); fma2(av[0][2], b2, wv0); fma2(av[0][3], b3, wv0);
        fma2(av[1][0], b0, wv1); fma2(av[1][1], b1, wv1); fma2(av[1][2], b2, wv1); fma2(av[1][3], b3, wv1);
    }

    const float sc = 0.35355339059327373f;  // 1/sqrt(8)
    float2 bq2 = *(const float2*)(bq + co);
    float2 bk2 = *(const float2*)(bk + co);
    float2 bv2 = *(const float2*)(bv + co);

    #pragma unroll
    for (int jj = 0; jj < 4; jj++) {
        float2 q0 = unp2(aq[0][jj]), q1 = unp2(aq[1][jj]);
        float2 k0 = unp2(ak[0][jj]), k1 = unp2(ak[1][jj]);
        float2 v0 = unp2(av[0][jj]), v1 = unp2(av[1][jj]);
        size_t p = (size_t)(p0 + pg * 8 + jj * 2);
        float2 o;
        o.x = (q0.x + bq2.x) * sc; o.y = (q1.x + bq2.y) * sc;
        *(float2*)(g_q + p * 64 + co) = o;
        o.x = (q0.y + bq2.x) * sc; o.y = (q1.y + bq2.y) * sc;
        *(float2*)(g_q + (p + 1) * 64 + co) = o;
        o.x = k0.x + bk2.x; o.y = k1.x + bk2.y;
        *(float2*)(g_k + p * 64 + co) = o;
        o.x = k0.y + bk2.x; o.y = k1.y + bk2.y;
        *(float2*)(g_k + (p + 1) * 64 + co) = o;
        o.x = v0.x + bv2.x; o.y = v1.x + bv2.y;
        *(float2*)(g_v + p * 64 + co) = o;
        o.x = v0.y + bv2.x; o.y = v1.y + bv2.y;
        *(float2*)(g_v + (p + 1) * 64 + co) = o;
    }
}

// ---------------- kernel 4: smem-tiled neighborhood attention + fused O-proj ----------------
#define AT_ROWS 288          // 3(h) * 6(w) * 16(z) halo rows
#define AT_PAD 68            // floats per row in smem (bank shift 4/row)
#define AT_SMEM_FLOATS (2 * AT_ROWS * AT_PAD + 1000 + 64 * AT_PAD)
#define AT_SMEM_BYTES  (AT_SMEM_FLOATS * 4)

__global__ __launch_bounds__(256) void k_attn(
    const float* __restrict__ Wo, const float* __restrict__ bo,
    const float* __restrict__ rpb, float* __restrict__ out)
{
    extern __shared__ float sm[];
    float* sK   = sm;
    float* sV   = sK + AT_ROWS * AT_PAD;
    float* sRpb = sV + AT_ROWS * AT_PAD;
    float* sO   = sRpb + 1000;          // [c][pos], pad AT_PAD

    int t = threadIdx.x;
    int p0 = blockIdx.x * 64;
    int h  = p0 >> 10;
    int w0 = (p0 >> 4) & 63;
    int sh = min(max(h - 1, 0), 61);
    int swmin = min(max(w0 - 1, 0), 61);

    // stage K/V halo (coalesced float4)
    for (int i = t; i < AT_ROWS * 16; i += 256) {
        int row = i >> 4, c4 = (i & 15) << 2;
        int ah = row / 96;
        int rem = row - ah * 96;
        int aw = rem >> 4;
        int zz = rem & 15;
        int gw = min(swmin + aw, 63);
        size_t gp = ((size_t)(((sh + ah) << 6) + gw) * 16 + zz) * 64 + c4;
        *(float4*)(sK + row * AT_PAD + c4) = *(const float4*)(g_k + gp);
        *(float4*)(sV + row * AT_PAD + c4) = *(const float4*)(g_v + gp);
    }
    for (int i = t; i < 1000; i += 256) sRpb[i] = rpb[i];
    __syncthreads();

    int pl = t & 63, hg = t >> 6;
    int w = w0 + (pl >> 4), z = pl & 15;
    int p = p0 + pl;
    int sw  = min(max(w - 1, 0), 61);
    int szv = min(max(z - 1, 0), 13);
    int awb = sw - swmin;
    int rbase0 = (sh - h + 2) * 25 + (sw - w + 2) * 5 + (szv - z + 2);

    for (int hh = 0; hh < 2; hh++) {
        int head = hg * 2 + hh;
        int off = head * 8;
        const float4* qp = (const float4*)(g_q + (size_t)p * 64 + off);
        float4 q0 = qp[0], q1 = qp[1];
        const float* rp = sRpb + head * 125 + rbase0;

        float lg[27];
        float mx = -1e30f;
        #pragma unroll
        for (int a = 0; a < 3; a++) {
            #pragma unroll
            for (int b = 0; b < 3; b++) {
                int rb = (a * 6 + awb + b) * 16 + szv;
                #pragma unroll
                for (int cz = 0; cz < 3; cz++) {
                    const float4* kp = (const float4*)(sK + (rb + cz) * AT_PAD + off);
                    float4 k0 = kp[0], k1 = kp[1];
                    float l = fmaf(q0.x, k0.x, fmaf(q0.y, k0.y, fmaf(q0.z, k0.z, fmaf(q0.w, k0.w,
                              fmaf(q1.x, k1.x, fmaf(q1.y, k1.y, fmaf(q1.z, k1.z, q1.w * k1.w)))))));
                    l += rp[a * 25 + b * 5 + cz];
                    lg[a * 9 + b * 3 + cz] = l;
                    mx = fmaxf(mx, l);
                }
            }
        }
        float se = 0.f;
        #pragma unroll
        for (int m = 0; m < 27; m++) { float e = __expf(lg[m] - mx); lg[m] = e; se += e; }
        float inv = 1.0f / se;

        float o[8];
        #pragma unroll
        for (int j = 0; j < 8; j++) o[j] = 0.f;
        #pragma unroll
        for (int a = 0; a < 3; a++) {
            #pragma unroll
            for (int b = 0; b < 3; b++) {
                int rb = (a * 6 + awb + b) * 16 + szv;
                #pragma unroll
                for (int cz = 0; cz < 3; cz++) {
                    const float4* vp = (const float4*)(sV + (rb + cz) * AT_PAD + off);
                    float4 v0 = vp[0], v1 = vp[1];
                    float wt = lg[a * 9 + b * 3 + cz] * inv;
                    o[0] = fmaf(wt, v0.x, o[0]); o[1] = fmaf(wt, v0.y, o[1]);
                    o[2] = fmaf(wt, v0.z, o[2]); o[3] = fmaf(wt, v0.w, o[3]);
                    o[4] = fmaf(wt, v1.x, o[4]); o[5] = fmaf(wt, v1.y, o[5]);
                    o[6] = fmaf(wt, v1.z, o[6]); o[7] = fmaf(wt, v1.w, o[7]);
                }
            }
        }
        #pragma unroll
        for (int j = 0; j < 8; j++) sO[(off + j) * AT_PAD + pl] = o[j];
    }
    __syncthreads();

    // fused output projection (f32x2): thread = (co, pos-quad of 16)
    int co = t & 63, pq = t >> 6;
    u64 acc[8];
    #pragma unroll
    for (int j = 0; j < 8; j++) acc[j] = 0ull;
    #pragma unroll 4
    for (int c = 0; c < 64; c++) {
        u64 wd = dup2(Wo[c * 64 + co]);
        const u64* op = (const u64*)(sO + c * AT_PAD + pq * 16);
        #pragma unroll
        for (int j = 0; j < 8; j++) fma2(acc[j], op[j], wd);
    }
    float bov = bo[co];
    float2* dst = (float2*)(out + (size_t)co * P + p0 + pq * 16);
    #pragma unroll
    for (int j = 0; j < 8; j++) {
        float2 r = unp2(acc[j]);
        r.x += bov; r.y += bov;
        dst[j] = r;
    }
}

// ---------------- launch ----------------
extern "C" void kernel_launch(void* const* d_in, const int* in_sizes, int n_in,
                              void* d_out, int out_size) {
    const float* x    = (const float*)d_in[0];
    const float* skip = (const float*)d_in[1];
    const float* Wq   = (const float*)d_in[2];
    const float* bq   = (const float*)d_in[3];
    const float* Wk   = (const float*)d_in[4];
    const float* bk   = (const float*)d_in[5];
    const float* Wv   = (const float*)d_in[6];
    const float* bv   = (const float*)d_in[7];
    const float* Wo   = (const float*)d_in[8];
    const float* bo   = (const float*)d_in[9];
    const float* rpb  = (const float*)d_in[10];
    float* out = (float*)d_out;

    static int attr_done = 0;
    if (!attr_done) {
        cudaFuncSetAttribute(k_attn, cudaFuncAttributeMaxDynamicSharedMemorySize, AT_SMEM_BYTES);
        attr_done = 1;
    }

    k_upsample<<<16384, 256>>>(x);
    k_stats<<<128, 256>>>(skip);
    k_qkv<<<1024, 256>>>(skip, Wq, bq, Wk, bk, Wv, bv);
    k_attn<<<1024, 256, AT_SMEM_BYTES>>>(Wo, bo, rpb, out);
}